// round 7
// baseline (speedup 1.0000x reference)
#include <cuda_runtime.h>

#define NUM_HEADS 4
#define D 100
#define D4 25
#define NW 39
#define ALPHA 0.3f
#define NT 320
#define WSTRIDE 104          // words row stride in floats; 104 mod 32 = 8 -> conflict-free split-half reads
#define TILE_FLOATS 4000
#define TILE_VEC4 1000

__device__ __forceinline__ float leaky(float p) {
    return fmaf(ALPHA, fminf(p, 0.f), fmaxf(p, 0.f));
}

__global__ __launch_bounds__(NT, 6)
void tse_kernel(const float* __restrict__ x,
                const float* __restrict__ w_att,
                const float* __restrict__ b_att,
                float* __restrict__ out,
                int n_groups)
{
    __shared__ float  s_words[NW * WSTRIDE];   // 16.2 KB
    __shared__ float4 s_type4[D4];
    __shared__ float4 s_wa4[NUM_HEADS * D4];
    __shared__ float4 s_ba4[NUM_HEADS * D4];
    __shared__ float4 s_e4[NW];                // exp(scores): {h0,h1,h2,h3} per word
    __shared__ float  s_inv[NUM_HEADS];
    __shared__ int    s_nz;

    const int t = threadIdx.x;
    const int g = blockIdx.x;
    if (g >= n_groups) return;

    // ---- phase 0: init + params (float4 copy; 100 pairs over 320 threads) ----
    if (t == 0) s_nz = 0;
    if (t < NUM_HEADS * D4) {
        s_wa4[t] = reinterpret_cast<const float4*>(w_att)[t];
        s_ba4[t] = reinterpret_cast<const float4*>(b_att)[t];
    }
    __syncthreads();

    // ---- phase 1: stage 40x100 tile (LDG.128 + STS.128) ----
    const float4* __restrict__ gx4 =
        reinterpret_cast<const float4*>(x + (size_t)g * TILE_FLOATS);
    bool flag = false;
    for (int i4 = t; i4 < TILE_VEC4; i4 += NT) {
        float4 v = gx4[i4];
        flag |= (v.x != 0.f) | (v.y != 0.f) | (v.z != 0.f) | (v.w != 0.f);
        int w = i4 / D4;           // word row (0 = type_emb)
        int j = i4 - w * D4;
        if (w == 0) s_type4[j] = v;
        else        *reinterpret_cast<float4*>(&s_words[(w - 1) * WSTRIDE + 4 * j]) = v;
    }
    unsigned any = __ballot_sync(0xffffffffu, flag);
    if ((t & 31) == 0 && any) atomicOr(&s_nz, 1);
    __syncthreads();

    // ---- phase 2: one thread per (h, n, d-half): 312 threads / all 10 warps ----
    {
        const int tt   = t < 312 ? t : 311;     // clamp so full-warp shfl is safe
        const int pair = tt >> 1;               // n + NW*h
        const int half = tt & 1;
        const int h = pair / NW;
        const int n = pair - h * NW;
        const int j0 = half ? 13 : 0;
        const int j1 = half ? 25 : 13;
        const float4* __restrict__ wr4 = reinterpret_cast<const float4*>(&s_words[n * WSTRIDE]);
        const float4* __restrict__ wa  = &s_wa4[h * D4];
        const float4* __restrict__ ba  = &s_ba4[h * D4];
        float acc = 0.f;
        #pragma unroll 1
        for (int j = j0; j < j1; ++j) {
            float4 w  = wr4[j];
            float4 ty = s_type4[j];
            float4 A  = wa[j];
            float4 B  = ba[j];
            acc = fmaf(ty.x, leaky(fmaf(w.x, A.x, B.x)), acc);
            acc = fmaf(ty.y, leaky(fmaf(w.y, A.y, B.y)), acc);
            acc = fmaf(ty.z, leaky(fmaf(w.z, A.z, B.z)), acc);
            acc = fmaf(ty.w, leaky(fmaf(w.w, A.w, B.w)), acc);
        }
        acc += __shfl_xor_sync(0xffffffffu, acc, 1);   // combine the two d-halves
        if (t < 312 && half == 0)
            ((float*)s_e4)[n * 4 + h] = __expf(acc);
    }
    __syncthreads();

    // ---- phase 3: per-head denominators, warp h reduces head h ----
    if (t < 4 * 32) {
        const int h = t >> 5, lane = t & 31;
        const float* ef = (const float*)s_e4;
        float v = (lane < NW) ? ef[lane * 4 + h] : 0.f;
        if (lane < NW - 32) v += ef[(lane + 32) * 4 + h];
        #pragma unroll
        for (int off = 16; off; off >>= 1)
            v += __shfl_down_sync(0xffffffffu, v, off);
        if (lane == 0) s_inv[h] = __fdividef(1.f, v);
    }
    __syncthreads();

    // ---- phase 4: one thread per (d, head-pair): 200 threads / 7 warps ----
    if (t < 2 * D) {
        int hp = 0, d = t;
        if (t >= D) { hp = 1; d = t - D; }
        const float* ef = (const float*)s_e4;
        float a0 = 0.f, a1 = 0.f;
        #pragma unroll 13
        for (int n = 0; n < NW; ++n) {
            float  w = s_words[n * WSTRIDE + d];
            float2 e = *reinterpret_cast<const float2*>(&ef[n * 4 + 2 * hp]);
            a0 = fmaf(e.x, w, a0);
            a1 = fmaf(e.y, w, a1);
        }
        float* __restrict__ go = out + (size_t)g * (NUM_HEADS * D);
        const int h0 = 2 * hp;
        if (s_nz) {
            go[h0 * D + d]       = a0 * s_inv[h0];
            go[(h0 + 1) * D + d] = a1 * s_inv[h0 + 1];
        } else {
            go[h0 * D + d] = 0.f;
            go[(h0 + 1) * D + d] = 0.f;
        }
    }
}

extern "C" void kernel_launch(void* const* d_in, const int* in_sizes, int n_in,
                              void* d_out, int out_size)
{
    const float* x     = (const float*)d_in[0];
    const float* w_att = (const float*)d_in[1];
    const float* b_att = (const float*)d_in[2];
    float* out = (float*)d_out;

    int n_groups = in_sizes[0] / TILE_FLOATS;   // B*T*E = 4800
    tse_kernel<<<n_groups, NT>>>(x, w_att, b_att, out, n_groups);
}

// round 8
// speedup vs baseline: 1.0430x; 1.0430x over previous
#include <cuda_runtime.h>

#define NUM_HEADS 4
#define D 100
#define D4 25
#define NW 39
#define NT 160
#define TILE_FLOATS 4000
#define TILE_VEC4 1000
#define C_ABS 0.5384615384615384f   // 0.35/0.65 : leaky(p) = 0.65*(p + C_ABS*|p|)
#define C_SCL 0.65f

__global__ __launch_bounds__(NT, 10)
void tse_kernel(const float* __restrict__ x,
                const float* __restrict__ w_att,
                const float* __restrict__ b_att,
                float* __restrict__ out,
                int n_groups)
{
    __shared__ float  s_words[NW * D];        // stride 100 ≡ 4 mod 32: conflict-free phases
    __shared__ float4 s_type4[D4];
    __shared__ float4 s_wa4[NUM_HEADS * D4];  // flat == w_att layout
    __shared__ float4 s_ba4[NUM_HEADS * D4];
    __shared__ float4 s_e4[NW];               // exp(scores): {h0,h1,h2,h3} per word
    __shared__ float  s_inv[NUM_HEADS];
    __shared__ int    s_nz;

    const int t = threadIdx.x;
    const int g = blockIdx.x;
    if (g >= n_groups) return;

    // ---- phase 0: init + params (float4 copy) ----
    if (t == 0) s_nz = 0;
    if (t < NUM_HEADS * D4) {
        s_wa4[t] = reinterpret_cast<const float4*>(w_att)[t];
        s_ba4[t] = reinterpret_cast<const float4*>(b_att)[t];
    }
    __syncthreads();

    // ---- phase 1: stage 40x100 tile (LDG.128 + STS.128, conflict-free) ----
    const float4* __restrict__ gx4 =
        reinterpret_cast<const float4*>(x + (size_t)g * TILE_FLOATS);
    bool flag = false;
    for (int i4 = t; i4 < TILE_VEC4; i4 += NT) {
        float4 v = gx4[i4];
        flag |= (v.x != 0.f) | (v.y != 0.f) | (v.z != 0.f) | (v.w != 0.f);
        int w = i4 / D4;           // word row (0 = type_emb)
        int j = i4 - w * D4;
        if (w == 0) s_type4[j] = v;
        else        *reinterpret_cast<float4*>(&s_words[(w - 1) * D + 4 * j]) = v;
    }
    unsigned any = __ballot_sync(0xffffffffu, flag);
    if ((t & 31) == 0 && any) atomicOr(&s_nz, 1);
    __syncthreads();

    // ---- phase 2: one thread per (h,n); 3 FFMA per element (abs-form leaky) ----
    if (t < NUM_HEADS * NW) {
        const int h = t / NW;
        const int n = t - h * NW;
        const float4* __restrict__ wr4 = reinterpret_cast<const float4*>(&s_words[n * D]);
        const float4* __restrict__ wa  = &s_wa4[h * D4];
        const float4* __restrict__ ba  = &s_ba4[h * D4];
        float acc0 = 0.f, acc1 = 0.f;
        #pragma unroll 2
        for (int j = 0; j < D4; ++j) {
            float4 w  = wr4[j];       // conflict-free spread
            float4 ty = s_type4[j];   // broadcast
            float4 A  = wa[j];        // broadcast within head span
            float4 B  = ba[j];
            float p, q;
            p = fmaf(w.x, A.x, B.x); q = fmaf(C_ABS, fabsf(p), p); acc0 = fmaf(ty.x, q, acc0);
            p = fmaf(w.y, A.y, B.y); q = fmaf(C_ABS, fabsf(p), p); acc1 = fmaf(ty.y, q, acc1);
            p = fmaf(w.z, A.z, B.z); q = fmaf(C_ABS, fabsf(p), p); acc0 = fmaf(ty.z, q, acc0);
            p = fmaf(w.w, A.w, B.w); q = fmaf(C_ABS, fabsf(p), p); acc1 = fmaf(ty.w, q, acc1);
        }
        ((float*)s_e4)[n * 4 + h] = __expf(C_SCL * (acc0 + acc1));
    }
    __syncthreads();

    // ---- phase 3: per-head denominators, warp h reduces head h ----
    if (t < 4 * 32) {
        const int h = t >> 5, lane = t & 31;
        const float* ef = (const float*)s_e4;
        float v = (lane < NW) ? ef[lane * 4 + h] : 0.f;
        if (lane < NW - 32) v += ef[(lane + 32) * 4 + h];
        #pragma unroll
        for (int off = 16; off; off >>= 1)
            v += __shfl_down_sync(0xffffffffu, v, off);
        if (lane == 0) s_inv[h] = __fdividef(1.f, v);
    }
    __syncthreads();

    // ---- phase 4: one thread per column d, all 4 heads ----
    if (t < D) {
        float a0 = 0.f, a1 = 0.f, a2 = 0.f, a3 = 0.f;
        #pragma unroll 13
        for (int n = 0; n < NW; ++n) {
            float  w = s_words[n * D + t];   // 1 conflict-free wf
            float4 e = s_e4[n];              // LDS.128 broadcast
            a0 = fmaf(e.x, w, a0);
            a1 = fmaf(e.y, w, a1);
            a2 = fmaf(e.z, w, a2);
            a3 = fmaf(e.w, w, a3);
        }
        float* __restrict__ go = out + (size_t)g * (NUM_HEADS * D);
        if (s_nz) {
            go[t]         = a0 * s_inv[0];
            go[D + t]     = a1 * s_inv[1];
            go[2 * D + t] = a2 * s_inv[2];
            go[3 * D + t] = a3 * s_inv[3];
        } else {
            go[t] = 0.f; go[D + t] = 0.f; go[2 * D + t] = 0.f; go[3 * D + t] = 0.f;
        }
    }
}

extern "C" void kernel_launch(void* const* d_in, const int* in_sizes, int n_in,
                              void* d_out, int out_size)
{
    const float* x     = (const float*)d_in[0];
    const float* w_att = (const float*)d_in[1];
    const float* b_att = (const float*)d_in[2];
    float* out = (float*)d_out;

    int n_groups = in_sizes[0] / TILE_FLOATS;   // B*T*E = 4800
    tse_kernel<<<n_groups, NT>>>(x, w_att, b_att, out, n_groups);
}

// round 10
// speedup vs baseline: 1.0796x; 1.0351x over previous
#include <cuda_runtime.h>

#define NUM_HEADS 4
#define D 100
#define D4 25
#define NW 39
#define NT 160
#define TILE_FLOATS 4000
#define TILE_VEC4 1000
#define C_ABS 0.5384615384615384f   // 0.35/0.65 : leaky(p) = 0.65*(p + C_ABS*|p|)
#define C_SCL 0.65f

__global__ __launch_bounds__(NT, 10)
void tse_kernel(const float* __restrict__ x,
                const float* __restrict__ w_att,
                const float* __restrict__ b_att,
                float* __restrict__ out,
                int n_groups)
{
    __shared__ float  s_words[NW * D];        // row stride 100 floats (16B-aligned rows)
    __shared__ float4 s_type4[D4];
    __shared__ float4 s_wa4[NUM_HEADS * D4];  // flat == w_att layout
    __shared__ float4 s_ba4[NUM_HEADS * D4];
    __shared__ float4 s_e4[NW];               // exp(scores): {h0,h1,h2,h3} per word
    __shared__ float  s_inv[NUM_HEADS];
    __shared__ int    s_nz;

    const int t = threadIdx.x;
    const int g = blockIdx.x;
    if (g >= n_groups) return;

    // ---- phase 0: init + params (float4 copy) ----
    if (t == 0) s_nz = 0;
    if (t < NUM_HEADS * D4) {
        s_wa4[t] = reinterpret_cast<const float4*>(w_att)[t];
        s_ba4[t] = reinterpret_cast<const float4*>(b_att)[t];
    }
    __syncthreads();

    // ---- phase 1: stage 40x100 tile (LDG.128 + STS.128) ----
    const float4* __restrict__ gx4 =
        reinterpret_cast<const float4*>(x + (size_t)g * TILE_FLOATS);
    bool flag = false;
    for (int i4 = t; i4 < TILE_VEC4; i4 += NT) {
        float4 v = gx4[i4];
        flag |= (v.x != 0.f) | (v.y != 0.f) | (v.z != 0.f) | (v.w != 0.f);
        int w = i4 / D4;           // word row (0 = type_emb)
        int j = i4 - w * D4;
        if (w == 0) s_type4[j] = v;
        else        *reinterpret_cast<float4*>(&s_words[(w - 1) * D + 4 * j]) = v;
    }
    unsigned any = __ballot_sync(0xffffffffu, flag);
    if ((t & 31) == 0 && any) atomicOr(&s_nz, 1);
    __syncthreads();

    // ---- phase 2: t = 4*n + h  (lane%4 = head) ----
    // Per warp per j: words = ONE wavefront (8 distinct 16B chunks, 4-lane
    // broadcast, bank bases {4n+4j} partition all 32 banks); wa/ba = 1 wf
    // each (4 distinct chunks, disjoint banks); ty = 1 wf broadcast.
    if (t < NUM_HEADS * NW) {
        const int n = t >> 2;
        const int h = t & 3;
        const float4* __restrict__ wr4 = reinterpret_cast<const float4*>(&s_words[n * D]);
        const float4* __restrict__ wa  = &s_wa4[h * D4];
        const float4* __restrict__ ba  = &s_ba4[h * D4];
        float acc0 = 0.f, acc1 = 0.f;
        #pragma unroll 2
        for (int j = 0; j < D4; ++j) {
            float4 w  = wr4[j];
            float4 ty = s_type4[j];
            float4 A  = wa[j];
            float4 B  = ba[j];
            float p, q;
            p = fmaf(w.x, A.x, B.x); q = fmaf(C_ABS, fabsf(p), p); acc0 = fmaf(ty.x, q, acc0);
            p = fmaf(w.y, A.y, B.y); q = fmaf(C_ABS, fabsf(p), p); acc1 = fmaf(ty.y, q, acc1);
            p = fmaf(w.z, A.z, B.z); q = fmaf(C_ABS, fabsf(p), p); acc0 = fmaf(ty.z, q, acc0);
            p = fmaf(w.w, A.w, B.w); q = fmaf(C_ABS, fabsf(p), p); acc1 = fmaf(ty.w, q, acc1);
        }
        ((float*)s_e4)[t] = __expf(C_SCL * (acc0 + acc1));   // contiguous STS
    }
    __syncthreads();

    // ---- phase 3: per-head denominators, warp h reduces head h ----
    if (t < 4 * 32) {
        const int h = t >> 5, lane = t & 31;
        const float* ef = (const float*)s_e4;
        float v = (lane < NW) ? ef[lane * 4 + h] : 0.f;
        if (lane < NW - 32) v += ef[(lane + 32) * 4 + h];
        #pragma unroll
        for (int off = 16; off; off >>= 1)
            v += __shfl_down_sync(0xffffffffu, v, off);
        if (lane == 0) s_inv[h] = __fdividef(1.f, v);
    }
    __syncthreads();

    // ---- phase 4: one thread per column d, all 4 heads ----
    if (t < D) {
        float a0 = 0.f, a1 = 0.f, a2 = 0.f, a3 = 0.f;
        #pragma unroll 13
        for (int n = 0; n < NW; ++n) {
            float  w = s_words[n * D + t];   // 1 wf spread
            float4 e = s_e4[n];              // LDS.128 broadcast
            a0 = fmaf(e.x, w, a0);
            a1 = fmaf(e.y, w, a1);
            a2 = fmaf(e.z, w, a2);
            a3 = fmaf(e.w, w, a3);
        }
        float* __restrict__ go = out + (size_t)g * (NUM_HEADS * D);
        if (s_nz) {
            go[t]         = a0 * s_inv[0];
            go[D + t]     = a1 * s_inv[1];
            go[2 * D + t] = a2 * s_inv[2];
            go[3 * D + t] = a3 * s_inv[3];
        } else {
            go[t] = 0.f; go[D + t] = 0.f; go[2 * D + t] = 0.f; go[3 * D + t] = 0.f;
        }
    }
}

extern "C" void kernel_launch(void* const* d_in, const int* in_sizes, int n_in,
                              void* d_out, int out_size)
{
    const float* x     = (const float*)d_in[0];
    const float* w_att = (const float*)d_in[1];
    const float* b_att = (const float*)d_in[2];
    float* out = (float*)d_out;

    int n_groups = in_sizes[0] / TILE_FLOATS;   // B*T*E = 4800
    tse_kernel<<<n_groups, NT>>>(x, w_att, b_att, out, n_groups);
}

// round 11
// speedup vs baseline: 1.3778x; 1.2762x over previous
#include <cuda_runtime.h>

#define NUM_HEADS 4
#define D 100
#define D4 25
#define NW 39
#define NT 160
#define TILE_FLOATS 4000
#define TILE_VEC4 1000
#define C_ABS 0.5384615384615384f   // 0.35/0.65 : leaky(p) = 0.65*(p + C_ABS*|p|)
#define C_SCL 0.65f

__global__ __launch_bounds__(NT, 7)
void tse_kernel(const float* __restrict__ x,
                const float* __restrict__ w_att,
                const float* __restrict__ b_att,
                float* __restrict__ out,
                int n_groups)
{
    __shared__ float  s_words[NW * D];      // 15.6 KB; float addr 100n+4j -> conflict-free
    __shared__ float4 s_part[NW * D4];      // 15.6 KB; [n][j] -> {h0,h1,h2,h3} partial scores
    __shared__ float4 s_type4[D4];
    __shared__ float4 s_e4[NW];             // exp(scores): {h0..h3} per word
    __shared__ float  s_inv[NUM_HEADS];
    __shared__ int    s_nz;

    const int t = threadIdx.x;
    const int g = blockIdx.x;
    if (g >= n_groups) return;

    // ---- params -> registers (L2-hot LDG.128; fixed column jp per thread) ----
    const int jp = t % D4;                  // float4 column owned in stage A
    const int nr = t / D4;                  // word-row class 0..5 (t<150)
    float4 wa0 = reinterpret_cast<const float4*>(w_att)[0 * D4 + jp];
    float4 wa1 = reinterpret_cast<const float4*>(w_att)[1 * D4 + jp];
    float4 wa2 = reinterpret_cast<const float4*>(w_att)[2 * D4 + jp];
    float4 wa3 = reinterpret_cast<const float4*>(w_att)[3 * D4 + jp];
    float4 ba0 = reinterpret_cast<const float4*>(b_att)[0 * D4 + jp];
    float4 ba1 = reinterpret_cast<const float4*>(b_att)[1 * D4 + jp];
    float4 ba2 = reinterpret_cast<const float4*>(b_att)[2 * D4 + jp];
    float4 ba3 = reinterpret_cast<const float4*>(b_att)[3 * D4 + jp];

    if (t == 0) s_nz = 0;
    __syncthreads();                        // s_nz init before atomicOr

    // ---- phase 1: stage 40x100 tile (LDG.128 + STS.128) ----
    const float4* __restrict__ gx4 =
        reinterpret_cast<const float4*>(x + (size_t)g * TILE_FLOATS);
    bool flag = false;
    for (int i4 = t; i4 < TILE_VEC4; i4 += NT) {
        float4 v = gx4[i4];
        flag |= (v.x != 0.f) | (v.y != 0.f) | (v.z != 0.f) | (v.w != 0.f);
        int w = i4 / D4;                    // word row (0 = type_emb)
        int j = i4 - w * D4;
        if (w == 0) s_type4[j] = v;
        else        *reinterpret_cast<float4*>(&s_words[(w - 1) * D + 4 * j]) = v;
    }
    unsigned any = __ballot_sync(0xffffffffu, flag);
    if ((t & 31) == 0 && any) atomicOr(&s_nz, 1);
    __syncthreads();

    // ---- stage A: partial scores. thread (jp, nr) handles n = nr + 6k. ----
    // Every LDS/STS byte is distinct: words LDS.128 (conflict-free) + partial
    // STS.128 (same addr pattern). Params + ty live in registers.
    if (t < 150) {
        const float4 ty = s_type4[jp];
        #pragma unroll
        for (int k = 0; k < 7; ++k) {
            const int n = nr + 6 * k;
            if (n < NW) {
                float4 w = *reinterpret_cast<const float4*>(&s_words[n * D + 4 * jp]);
                float p, q;
                float a0, a1, a2, a3;
                p = fmaf(w.x, wa0.x, ba0.x); q = fmaf(C_ABS, fabsf(p), p); a0 = ty.x * q;
                p = fmaf(w.y, wa0.y, ba0.y); q = fmaf(C_ABS, fabsf(p), p); a0 = fmaf(ty.y, q, a0);
                p = fmaf(w.z, wa0.z, ba0.z); q = fmaf(C_ABS, fabsf(p), p); a0 = fmaf(ty.z, q, a0);
                p = fmaf(w.w, wa0.w, ba0.w); q = fmaf(C_ABS, fabsf(p), p); a0 = fmaf(ty.w, q, a0);
                p = fmaf(w.x, wa1.x, ba1.x); q = fmaf(C_ABS, fabsf(p), p); a1 = ty.x * q;
                p = fmaf(w.y, wa1.y, ba1.y); q = fmaf(C_ABS, fabsf(p), p); a1 = fmaf(ty.y, q, a1);
                p = fmaf(w.z, wa1.z, ba1.z); q = fmaf(C_ABS, fabsf(p), p); a1 = fmaf(ty.z, q, a1);
                p = fmaf(w.w, wa1.w, ba1.w); q = fmaf(C_ABS, fabsf(p), p); a1 = fmaf(ty.w, q, a1);
                p = fmaf(w.x, wa2.x, ba2.x); q = fmaf(C_ABS, fabsf(p), p); a2 = ty.x * q;
                p = fmaf(w.y, wa2.y, ba2.y); q = fmaf(C_ABS, fabsf(p), p); a2 = fmaf(ty.y, q, a2);
                p = fmaf(w.z, wa2.z, ba2.z); q = fmaf(C_ABS, fabsf(p), p); a2 = fmaf(ty.z, q, a2);
                p = fmaf(w.w, wa2.w, ba2.w); q = fmaf(C_ABS, fabsf(p), p); a2 = fmaf(ty.w, q, a2);
                p = fmaf(w.x, wa3.x, ba3.x); q = fmaf(C_ABS, fabsf(p), p); a3 = ty.x * q;
                p = fmaf(w.y, wa3.y, ba3.y); q = fmaf(C_ABS, fabsf(p), p); a3 = fmaf(ty.y, q, a3);
                p = fmaf(w.z, wa3.z, ba3.z); q = fmaf(C_ABS, fabsf(p), p); a3 = fmaf(ty.z, q, a3);
                p = fmaf(w.w, wa3.w, ba3.w); q = fmaf(C_ABS, fabsf(p), p); a3 = fmaf(ty.w, q, a3);
                s_part[n * D4 + jp] = make_float4(a0, a1, a2, a3);
            }
        }
    }
    __syncthreads();

    // ---- stage B: score(h,n) = sum_j part[n][j][h]; bank = (t' + 4j) % 32 ----
    if (t < NUM_HEADS * NW) {
        const float* pf = (const float*)s_part;
        const int n = t >> 2;
        const int h = t & 3;
        const float* row = pf + n * 100 + h;
        float s0 = 0.f, s1 = 0.f;
        #pragma unroll
        for (int j = 0; j < 24; j += 2) {
            s0 += row[4 * j];
            s1 += row[4 * (j + 1)];
        }
        s0 += row[4 * 24];
        ((float*)s_e4)[t] = __expf(C_SCL * (s0 + s1));   // contiguous STS
    }
    __syncthreads();

    // ---- phase 3: per-head denominators, warp h reduces head h ----
    if (t < 4 * 32) {
        const int h = t >> 5, lane = t & 31;
        const float* ef = (const float*)s_e4;
        float v = (lane < NW) ? ef[lane * 4 + h] : 0.f;
        if (lane < NW - 32) v += ef[(lane + 32) * 4 + h];
        #pragma unroll
        for (int off = 16; off; off >>= 1)
            v += __shfl_down_sync(0xffffffffu, v, off);
        if (lane == 0) s_inv[h] = __fdividef(1.f, v);
    }
    __syncthreads();

    // ---- phase 4: one thread per column d, all 4 heads ----
    if (t < D) {
        float a0 = 0.f, a1 = 0.f, a2 = 0.f, a3 = 0.f;
        #pragma unroll 13
        for (int n = 0; n < NW; ++n) {
            float  w = s_words[n * D + t];
            float4 e = s_e4[n];
            a0 = fmaf(e.x, w, a0);
            a1 = fmaf(e.y, w, a1);
            a2 = fmaf(e.z, w, a2);
            a3 = fmaf(e.w, w, a3);
        }
        float* __restrict__ go = out + (size_t)g * (NUM_HEADS * D);
        if (s_nz) {
            go[t]         = a0 * s_inv[0];
            go[D + t]     = a1 * s_inv[1];
            go[2 * D + t] = a2 * s_inv[2];
            go[3 * D + t] = a3 * s_inv[3];
        } else {
            go[t] = 0.f; go[D + t] = 0.f; go[2 * D + t] = 0.f; go[3 * D + t] = 0.f;
        }
    }
}

extern "C" void kernel_launch(void* const* d_in, const int* in_sizes, int n_in,
                              void* d_out, int out_size)
{
    const float* x     = (const float*)d_in[0];
    const float* w_att = (const float*)d_in[1];
    const float* b_att = (const float*)d_in[2];
    float* out = (float*)d_out;

    int n_groups = in_sizes[0] / TILE_FLOATS;   // B*T*E = 4800
    tse_kernel<<<n_groups, NT>>>(x, w_att, b_att, out, n_groups);
}

// round 12
// speedup vs baseline: 1.3873x; 1.0069x over previous
#include <cuda_runtime.h>

#define NUM_HEADS 4
#define D 100
#define D4 25
#define NW 39
#define NT 160
#define TILE_FLOATS 4000
#define TILE_VEC4 1000
#define C_ABS 0.5384615384615384f   // 0.35/0.65 : leaky(p) = 0.65*(p + C_ABS*|p|)
#define C_SCL 0.65f

__global__ __launch_bounds__(NT, 7)
void tse_kernel(const float* __restrict__ x,
                const float* __restrict__ w_att,
                const float* __restrict__ b_att,
                float* __restrict__ out,
                int n_groups)
{
    __shared__ float  s_words[NW * D];      // 15.6 KB; float addr 100n+4j
    __shared__ float4 s_part[NW * D4];      // 15.6 KB; [n][j] -> {h0..h3} partial scores
    __shared__ float4 s_type4[D4];
    __shared__ float4 s_e4[NW];             // exp(scores): {h0..h3} per word
    __shared__ float  s_inv[NUM_HEADS];
    __shared__ int    s_nz;

    const int t = threadIdx.x;
    const int g = blockIdx.x;
    if (g >= n_groups) return;

    // ---- params -> registers (L2/L1-hot LDG.128; fixed column jp per thread) ----
    const int jp = t % D4;                  // float4 column owned in stage A
    const int nr = t / D4;                  // word-row class 0..5 (t<150)
    float4 wa0 = reinterpret_cast<const float4*>(w_att)[0 * D4 + jp];
    float4 wa1 = reinterpret_cast<const float4*>(w_att)[1 * D4 + jp];
    float4 wa2 = reinterpret_cast<const float4*>(w_att)[2 * D4 + jp];
    float4 wa3 = reinterpret_cast<const float4*>(w_att)[3 * D4 + jp];
    float4 ba0 = reinterpret_cast<const float4*>(b_att)[0 * D4 + jp];
    float4 ba1 = reinterpret_cast<const float4*>(b_att)[1 * D4 + jp];
    float4 ba2 = reinterpret_cast<const float4*>(b_att)[2 * D4 + jp];
    float4 ba3 = reinterpret_cast<const float4*>(b_att)[3 * D4 + jp];

    if (t == 0) s_nz = 0;
    __syncthreads();                        // s_nz init before atomicOr

    // ---- phase 1: stage 40x100 tile (LDG.128 + STS.128) ----
    const float4* __restrict__ gx4 =
        reinterpret_cast<const float4*>(x + (size_t)g * TILE_FLOATS);
    bool flag = false;
    for (int i4 = t; i4 < TILE_VEC4; i4 += NT) {
        float4 v = gx4[i4];
        flag |= (v.x != 0.f) | (v.y != 0.f) | (v.z != 0.f) | (v.w != 0.f);
        int w = i4 / D4;                    // word row (0 = type_emb)
        int j = i4 - w * D4;
        if (w == 0) s_type4[j] = v;
        else        *reinterpret_cast<float4*>(&s_words[(w - 1) * D + 4 * j]) = v;
    }
    unsigned any = __ballot_sync(0xffffffffu, flag);
    if ((t & 31) == 0 && any) atomicOr(&s_nz, 1);
    __syncthreads();

    // ---- stage A: partial scores; thread (jp, nr) handles n = nr + 6k ----
    if (t < 150) {
        const float4 ty = s_type4[jp];
        #pragma unroll
        for (int k = 0; k < 7; ++k) {
            const int n = nr + 6 * k;
            if (n < NW) {
                float4 w = *reinterpret_cast<const float4*>(&s_words[n * D + 4 * jp]);
                float p, q;
                float a0, a1, a2, a3;
                p = fmaf(w.x, wa0.x, ba0.x); q = fmaf(C_ABS, fabsf(p), p); a0 = ty.x * q;
                p = fmaf(w.y, wa0.y, ba0.y); q = fmaf(C_ABS, fabsf(p), p); a0 = fmaf(ty.y, q, a0);
                p = fmaf(w.z, wa0.z, ba0.z); q = fmaf(C_ABS, fabsf(p), p); a0 = fmaf(ty.z, q, a0);
                p = fmaf(w.w, wa0.w, ba0.w); q = fmaf(C_ABS, fabsf(p), p); a0 = fmaf(ty.w, q, a0);
                p = fmaf(w.x, wa1.x, ba1.x); q = fmaf(C_ABS, fabsf(p), p); a1 = ty.x * q;
                p = fmaf(w.y, wa1.y, ba1.y); q = fmaf(C_ABS, fabsf(p), p); a1 = fmaf(ty.y, q, a1);
                p = fmaf(w.z, wa1.z, ba1.z); q = fmaf(C_ABS, fabsf(p), p); a1 = fmaf(ty.z, q, a1);
                p = fmaf(w.w, wa1.w, ba1.w); q = fmaf(C_ABS, fabsf(p), p); a1 = fmaf(ty.w, q, a1);
                p = fmaf(w.x, wa2.x, ba2.x); q = fmaf(C_ABS, fabsf(p), p); a2 = ty.x * q;
                p = fmaf(w.y, wa2.y, ba2.y); q = fmaf(C_ABS, fabsf(p), p); a2 = fmaf(ty.y, q, a2);
                p = fmaf(w.z, wa2.z, ba2.z); q = fmaf(C_ABS, fabsf(p), p); a2 = fmaf(ty.z, q, a2);
                p = fmaf(w.w, wa2.w, ba2.w); q = fmaf(C_ABS, fabsf(p), p); a2 = fmaf(ty.w, q, a2);
                p = fmaf(w.x, wa3.x, ba3.x); q = fmaf(C_ABS, fabsf(p), p); a3 = ty.x * q;
                p = fmaf(w.y, wa3.y, ba3.y); q = fmaf(C_ABS, fabsf(p), p); a3 = fmaf(ty.y, q, a3);
                p = fmaf(w.z, wa3.z, ba3.z); q = fmaf(C_ABS, fabsf(p), p); a3 = fmaf(ty.z, q, a3);
                p = fmaf(w.w, wa3.w, ba3.w); q = fmaf(C_ABS, fabsf(p), p); a3 = fmaf(ty.w, q, a3);
                s_part[n * D4 + jp] = make_float4(a0, a1, a2, a3);
            }
        }
    }
    __syncthreads();

    // ---- stage B: score(h,n) = sum_j part[n][j][h] ----
    if (t < NUM_HEADS * NW) {
        const float* pf = (const float*)s_part;
        const int n = t >> 2;
        const int h = t & 3;
        const float* row = pf + n * 100 + h;
        float s0 = 0.f, s1 = 0.f;
        #pragma unroll
        for (int j = 0; j < 24; j += 2) {
            s0 += row[4 * j];
            s1 += row[4 * (j + 1)];
        }
        s0 += row[4 * 24];
        ((float*)s_e4)[t] = __expf(C_SCL * (s0 + s1));   // contiguous STS
    }
    __syncthreads();

    // ---- phase 3: per-head denominators, warp h reduces head h ----
    if (t < 4 * 32) {
        const int h = t >> 5, lane = t & 31;
        const float* ef = (const float*)s_e4;
        float v = (lane < NW) ? ef[lane * 4 + h] : 0.f;
        if (lane < NW - 32) v += ef[(lane + 32) * 4 + h];
        #pragma unroll
        for (int off = 16; off; off >>= 1)
            v += __shfl_down_sync(0xffffffffu, v, off);
        if (lane == 0) s_inv[h] = __fdividef(1.f, v);
    }
    __syncthreads();

    // ---- phase 4: 25-thread register tile. thread jp -> d = 4jp..4jp+3, all heads ----
    // Per n: one LDS.128 words (400B distinct) + one LDS.128 e4 (400B writeback)
    // vs 2000B/n before. 16 FMA per 32 loaded bytes.
    if (t < D4) {
        float4 o0 = make_float4(0.f, 0.f, 0.f, 0.f);
        float4 o1 = o0, o2 = o0, o3 = o0;
        #pragma unroll 13
        for (int n = 0; n < NW; ++n) {
            float4 w = *reinterpret_cast<const float4*>(&s_words[n * D + 4 * t]);
            float4 e = s_e4[n];
            o0.x = fmaf(e.x, w.x, o0.x); o0.y = fmaf(e.x, w.y, o0.y);
            o0.z = fmaf(e.x, w.z, o0.z); o0.w = fmaf(e.x, w.w, o0.w);
            o1.x = fmaf(e.y, w.x, o1.x); o1.y = fmaf(e.y, w.y, o1.y);
            o1.z = fmaf(e.y, w.z, o1.z); o1.w = fmaf(e.y, w.w, o1.w);
            o2.x = fmaf(e.z, w.x, o2.x); o2.y = fmaf(e.z, w.y, o2.y);
            o2.z = fmaf(e.z, w.z, o2.z); o2.w = fmaf(e.z, w.w, o2.w);
            o3.x = fmaf(e.w, w.x, o3.x); o3.y = fmaf(e.w, w.y, o3.y);
            o3.z = fmaf(e.w, w.z, o3.z); o3.w = fmaf(e.w, w.w, o3.w);
        }
        float4* __restrict__ go4 =
            reinterpret_cast<float4*>(out + (size_t)g * (NUM_HEADS * D));
        const float4 zero = make_float4(0.f, 0.f, 0.f, 0.f);
        if (s_nz) {
            float i0 = s_inv[0], i1 = s_inv[1], i2 = s_inv[2], i3 = s_inv[3];
            go4[0 * D4 + t] = make_float4(o0.x * i0, o0.y * i0, o0.z * i0, o0.w * i0);
            go4[1 * D4 + t] = make_float4(o1.x * i1, o1.y * i1, o1.z * i1, o1.w * i1);
            go4[2 * D4 + t] = make_float4(o2.x * i2, o2.y * i2, o2.z * i2, o2.w * i2);
            go4[3 * D4 + t] = make_float4(o3.x * i3, o3.y * i3, o3.z * i3, o3.w * i3);
        } else {
            go4[0 * D4 + t] = zero;
            go4[1 * D4 + t] = zero;
            go4[2 * D4 + t] = zero;
            go4[3 * D4 + t] = zero;
        }
    }
}

extern "C" void kernel_launch(void* const* d_in, const int* in_sizes, int n_in,
                              void* d_out, int out_size)
{
    const float* x     = (const float*)d_in[0];
    const float* w_att = (const float*)d_in[1];
    const float* b_att = (const float*)d_in[2];
    float* out = (float*)d_out;

    int n_groups = in_sizes[0] / TILE_FLOATS;   // B*T*E = 4800
    tse_kernel<<<n_groups, NT>>>(x, w_att, b_att, out, n_groups);
}